// round 16
// baseline (speedup 1.0000x reference)
#include <cuda_runtime.h>
#include <stdint.h>

#define BSZ  16384
#define KC   8192
#define MAXC 100
#define MINC 20
#define NT   256
#define PER  32
#define CAP  512
#define HTHR 0xBFC00000u   // raw bits of -1.5f:  f >= -1.5  <=>  u <= HTHR

__device__ __forceinline__ uint32_t fkey(uint32_t u) {
    return u ^ (uint32_t)(((int)u >> 31) | (int)0x80000000);   // order-preserving
}

// sum over threads with tid' > tid (block exclusive suffix). 2 barriers.
__device__ __forceinline__ int block_suffix_excl(int v, int tid, volatile int* wtmp) {
    int lane = tid & 31, w = tid >> 5;
    int x = v;
    #pragma unroll
    for (int off = 1; off < 32; off <<= 1) {
        int t = __shfl_down_sync(0xFFFFFFFFu, x, off);
        if (lane + off < 32) x += t;
    }
    if (lane == 0) wtmp[w] = x;
    __syncthreads();
    int above = 0;
    #pragma unroll
    for (int j = 0; j < 8; j++) above += (j > w) ? wtmp[j] : 0;
    __syncthreads();
    return above + (x - v);
}

// sum over threads with tid' < tid (block exclusive prefix). 2 barriers.
__device__ __forceinline__ int block_prefix_excl(int v, int tid, volatile int* wtmp) {
    int lane = tid & 31, w = tid >> 5;
    int x = v;
    #pragma unroll
    for (int off = 1; off < 32; off <<= 1) {
        int t = __shfl_up_sync(0xFFFFFFFFu, x, off);
        if (lane >= off) x += t;
    }
    if (lane == 31) wtmp[w] = x;
    __syncthreads();
    int below = 0;
    #pragma unroll
    for (int j = 0; j < 8; j++) below += (j < w) ? wtmp[j] : 0;
    __syncthreads();
    return below + (x - v);
}

__global__ __launch_bounds__(NT, 5) void retention_kernel(
    const float* __restrict__ logits, float* __restrict__ out)
{
    __shared__ uint64_t cc[CAP];        // 4 KB: (key<<16) | (8191-idx); key sign = bit 47
    __shared__ uint32_t bitmap[NT];     // 1 KB selection bitmap
    __shared__ int      hist[2048];     // 8 KB (slow path only)
    __shared__ int      wtmp[8];
    __shared__ int      sctl[4];
    __shared__ int      s_above, sW;

    const int row  = blockIdx.x;
    const int tid  = threadIdx.x;

    bitmap[tid] = 0;
    if (tid == 0) { sW = 0; s_above = 0; }
    __syncthreads();

    // ---- Phase 0: stream raw bits. 4 chained compares + 1 rare branch per uint4 ----
    const uint4* in4 = (const uint4*)(logits + (size_t)row * KC);
    #pragma unroll
    for (int half = 0; half < 2; half++) {
        uint4 u[4];
        #pragma unroll
        for (int i = 0; i < 4; i++) u[i] = in4[tid + (half * 4 + i) * NT];
        #pragma unroll
        for (int i = 0; i < 4; i++) {
            if (u[i].x <= HTHR || u[i].y <= HTHR || u[i].z <= HTHR || u[i].w <= HTHR) {
                int v = tid + (half * 4 + i) * NT;       // ~4.6% of uint4s
                #pragma unroll
                for (int c = 0; c < 4; c++) {
                    uint32_t raw = (c == 0) ? u[i].x : (c == 1) ? u[i].y : (c == 2) ? u[i].z : u[i].w;
                    if (raw <= HTHR) {
                        int pos = atomicAdd(&sW, 1);
                        if (pos < CAP)
                            cc[pos] = ((uint64_t)fkey(raw) << 16) | (uint32_t)(8191 - (v * 4 + c));
                    }
                }
            }
        }
    }
    __syncthreads();

    int W = sW;
    int ktrain = 0;
    bool done = false;

    if (W <= CAP) {
        // count(logit >= 0) from candidates: every such element passed the prefilter
        int cnt = 0;
        for (int i = tid; i < W; i += NT) cnt += (int)((cc[i] >> 47) & 1ull);
        cnt = __reduce_add_sync(0xFFFFFFFFu, cnt);
        if ((tid & 31) == 0) atomicAdd(&s_above, cnt);
        __syncthreads();
        ktrain = min(max(s_above, MINC), MAXC);

        if (W >= ktrain) {
            // ======== FAST PATH: exact top-k by pairwise rank (no barriers) =====
            for (int i = tid; i < W; i += NT) {
                uint64_t ci = cc[i];
                int rank = 0;
                #pragma unroll 4
                for (int j = 0; j < W; j++) rank += (cc[j] > ci);   // broadcast LDS.64
                if (rank < ktrain) {
                    int di = 8191 - (int)(ci & 0xFFFFu);
                    atomicOr(&bitmap[di >> 5], 1u << (di & 31));
                }
            }
            __syncthreads();
            done = true;
        }
    }

    if (!done) {
        // ======== SLOW PATH (prefilter miss — ~never): exact from global ========
        const float* in1 = (const float*)in4;
        const int4 z4 = make_int4(0, 0, 0, 0);
        ((int4*)hist)[2 * tid] = z4; ((int4*)hist)[2 * tid + 1] = z4;
        if (tid == 0) s_above = 0;
        __syncthreads();
        for (int i = tid; i < KC; i += NT)
            atomicAdd(&hist[fkey(__float_as_uint(in1[i])) >> 21], 1);
        __syncthreads();
        int h[8];
        {
            int4 a = ((int4*)hist)[2 * tid];
            int4 bb = ((int4*)hist)[2 * tid + 1];
            h[0]=a.x;h[1]=a.y;h[2]=a.z;h[3]=a.w;h[4]=bb.x;h[5]=bb.y;h[6]=bb.z;h[7]=bb.w;
            ((int4*)hist)[2 * tid] = z4; ((int4*)hist)[2 * tid + 1] = z4;
        }
        int local = h[0]+h[1]+h[2]+h[3]+h[4]+h[5]+h[6]+h[7];
        int above = block_suffix_excl(local, tid, wtmp);
        if (tid == 128) s_above = above + local;     // bins >= 1024 <=> logit >= 0
        __syncthreads();
        ktrain = min(max(s_above, MINC), MAXC);
        if (above < ktrain && above + local >= ktrain) {
            int run = above;
            for (int j = 7; j >= 0; j--) {
                int c = h[j];
                if (run < ktrain && run + c >= ktrain) { sctl[0] = tid * 8 + j; sctl[1] = ktrain - run; }
                run += c;
            }
        }
        __syncthreads();
        const uint32_t b = (uint32_t)sctl[0];

        if (tid == 0) sW = 0;
        __syncthreads();
        for (int i = tid; i < KC; i += NT) {
            uint32_t k2 = fkey(__float_as_uint(in1[i]));
            if ((k2 >> 21) >= b) {
                int pos = atomicAdd(&sW, 1);
                if (pos < CAP) cc[pos] = ((uint64_t)k2 << 16) | (uint32_t)(8191 - i);
            }
        }
        __syncthreads();
        W = sW;

        if (W <= CAP) {
            for (int i = tid; i < W; i += NT) {
                uint64_t ci = cc[i];
                int rank = 0;
                for (int j = 0; j < W; j++) rank += (cc[j] > ci);
                if (rank < ktrain) {
                    int di = 8191 - (int)(ci & 0xFFFFu);
                    atomicOr(&bitmap[di >> 5], 1u << (di & 31));
                }
            }
            __syncthreads();
        } else {
            // ---- ULTRA fallback: histogram refine to exact threshold ----
            const int need = sctl[1];
            for (int i = tid; i < KC; i += NT) {
                uint32_t k2 = fkey(__float_as_uint(in1[i]));
                if ((k2 >> 21) == b) atomicAdd(&hist[(k2 >> 10) & 0x7FF], 1);
            }
            __syncthreads();
            {
                int4 a = ((int4*)hist)[2 * tid];
                int4 bb = ((int4*)hist)[2 * tid + 1];
                h[0]=a.x;h[1]=a.y;h[2]=a.z;h[3]=a.w;h[4]=bb.x;h[5]=bb.y;h[6]=bb.z;h[7]=bb.w;
                ((int4*)hist)[2 * tid] = z4; ((int4*)hist)[2 * tid + 1] = z4;
            }
            local = h[0]+h[1]+h[2]+h[3]+h[4]+h[5]+h[6]+h[7];
            above = block_suffix_excl(local, tid, wtmp);
            if (above < need && above + local >= need) {
                int run = above;
                for (int j = 7; j >= 0; j--) {
                    int c = h[j];
                    if (run < need && run + c >= need) { sctl[2] = tid * 8 + j; sctl[3] = need - run; }
                    run += c;
                }
            }
            __syncthreads();
            const int need2 = sctl[3];
            const uint32_t pref22 = (b << 11) | (uint32_t)sctl[2];

            for (int i = tid; i < KC; i += NT) {
                uint32_t k2 = fkey(__float_as_uint(in1[i]));
                if ((k2 >> 10) == pref22) atomicAdd(&hist[k2 & 0x3FF], 1);
            }
            __syncthreads();
            {
                int4 a = ((int4*)hist)[tid];
                int h4[4] = {a.x, a.y, a.z, a.w};
                ((int4*)hist)[tid] = z4;
                int l3 = h4[0]+h4[1]+h4[2]+h4[3];
                int ab3 = block_suffix_excl(l3, tid, wtmp);
                if (ab3 < need2 && ab3 + l3 >= need2) {
                    int run = ab3;
                    for (int j = 3; j >= 0; j--) {
                        int c = h4[j];
                        if (run < need2 && run + c >= need2) { sctl[0] = tid * 4 + j; sctl[1] = need2 - run; }
                        run += c;
                    }
                }
            }
            __syncthreads();
            const uint32_t T = (pref22 << 10) | (uint32_t)sctl[0];
            const int need_eq = sctl[1];

            uint16_t* cidx = (uint16_t*)cc;     // scratch reuse
            if (tid == 0) sW = 0;
            __syncthreads();
            for (int i = tid; i < KC; i += NT) {
                uint32_t k2 = fkey(__float_as_uint(in1[i]));
                if (k2 > T) atomicOr(&bitmap[i >> 5], 1u << (i & 31));
                else if (k2 == T) {
                    int pos = atomicAdd(&sW, 1);
                    if (pos < CAP) cidx[pos] = (uint16_t)i;
                }
            }
            __syncthreads();
            int We = min(sW, CAP);
            for (int i = tid; i < We; i += NT) {
                int di = cidx[i];
                int rank = 0;
                for (int j = 0; j < We; j++) rank += ((int)cidx[j] < di);
                if (rank < need_eq) atomicOr(&bitmap[di >> 5], 1u << (di & 31));
            }
            __syncthreads();
        }
    }

    // ---- Emission: bitmap popcount + block prefix scan + bit walk ----
    uint32_t wbits = bitmap[tid];
    int cnt = __popc(wbits);
    int pos = block_prefix_excl(cnt, tid, wtmp);

    float* __restrict__ bs_out  = out;
    float* __restrict__ cls_out = out + (size_t)BSZ * MAXC;
    float* __restrict__ msk_out = out + (size_t)2 * BSZ * MAXC;
    const size_t rbase = (size_t)row * MAXC;

    while (wbits) {
        int bit = __ffs(wbits) - 1;
        wbits &= wbits - 1;
        cls_out[rbase + pos] = (float)(tid * 32 + bit);
        pos++;
    }

    // ---- Padding / bs_idx / mask ----
    if (tid < MAXC) {
        bs_out[rbase + tid] = (tid < ktrain) ? (float)row : -1.0f;
        if (tid >= ktrain) cls_out[rbase + tid] = -1.0f;
        msk_out[rbase + tid] = (tid < ktrain) ? 1.0f : 0.0f;
    }
}

extern "C" void kernel_launch(void* const* d_in, const int* in_sizes, int n_in,
                              void* d_out, int out_size)
{
    const float* logits = (const float*)d_in[0];
    float* out = (float*)d_out;
    retention_kernel<<<BSZ, NT>>>(logits, out);
}

// round 17
// speedup vs baseline: 1.0492x; 1.0492x over previous
#include <cuda_runtime.h>
#include <stdint.h>

#define BSZ  16384
#define KC   8192
#define MAXC 100
#define MINC 20
#define NT   256
#define PER  32
#define CAP  512
#define HTHR 0xBFC00000u   // raw bits of -1.5f:  f >= -1.5  <=>  u <= HTHR

__device__ __forceinline__ uint32_t fkey(uint32_t u) {
    return u ^ (uint32_t)(((int)u >> 31) | (int)0x80000000);   // order-preserving
}

// sum over threads with tid' > tid (block exclusive suffix). 2 barriers.
__device__ __forceinline__ int block_suffix_excl(int v, int tid, volatile int* wtmp) {
    int lane = tid & 31, w = tid >> 5;
    int x = v;
    #pragma unroll
    for (int off = 1; off < 32; off <<= 1) {
        int t = __shfl_down_sync(0xFFFFFFFFu, x, off);
        if (lane + off < 32) x += t;
    }
    if (lane == 0) wtmp[w] = x;
    __syncthreads();
    int above = 0;
    #pragma unroll
    for (int j = 0; j < 8; j++) above += (j > w) ? wtmp[j] : 0;
    __syncthreads();
    return above + (x - v);
}

// sum over threads with tid' < tid (block exclusive prefix). 2 barriers.
__device__ __forceinline__ int block_prefix_excl(int v, int tid, volatile int* wtmp) {
    int lane = tid & 31, w = tid >> 5;
    int x = v;
    #pragma unroll
    for (int off = 1; off < 32; off <<= 1) {
        int t = __shfl_up_sync(0xFFFFFFFFu, x, off);
        if (lane >= off) x += t;
    }
    if (lane == 31) wtmp[w] = x;
    __syncthreads();
    int below = 0;
    #pragma unroll
    for (int j = 0; j < 8; j++) below += (j < w) ? wtmp[j] : 0;
    __syncthreads();
    return below + (x - v);
}

__global__ __launch_bounds__(NT, 5) void retention_kernel(
    const float* __restrict__ logits, float* __restrict__ out)
{
    __shared__ uint64_t cc[CAP];        // 4 KB: (key<<16) | (8191-idx); key sign = bit 47
    __shared__ uint32_t bitmap[NT];     // 1 KB selection bitmap
    __shared__ int      hist[2048];     // 8 KB (slow path only)
    __shared__ int      wtmp[8];
    __shared__ int      sctl[4];
    __shared__ int      s_above, sW;

    const int row  = blockIdx.x;
    const int tid  = threadIdx.x;

    bitmap[tid] = 0;
    if (tid == 0) { sW = 0; s_above = 0; }
    __syncthreads();

    // ---- Phase 0: branchless stream. Per uint4: 4 chained compares -> 1 hit bit ----
    const uint4* in4 = (const uint4*)(logits + (size_t)row * KC);
    uint32_t hitm = 0;
    #pragma unroll
    for (int half = 0; half < 2; half++) {
        uint4 u[4];
        #pragma unroll
        for (int i = 0; i < 4; i++) u[i] = in4[tid + (half * 4 + i) * NT];
        #pragma unroll
        for (int i = 0; i < 4; i++) {
            if (u[i].x <= HTHR || u[i].y <= HTHR || u[i].z <= HTHR || u[i].w <= HTHR)
                hitm |= 1u << (half * 4 + i);       // predicated OR, immediate shift
        }
    }

    // ---- Deferred compaction: ~0.37 set bits/thread, reload from L2-hot row ----
    while (hitm) {
        int b = __ffs(hitm) - 1;
        hitm &= hitm - 1;
        int v = tid + b * NT;
        uint4 u = in4[v];                           // L2 hit (~234 cyc, rare)
        #pragma unroll
        for (int c = 0; c < 4; c++) {
            uint32_t raw = (c == 0) ? u.x : (c == 1) ? u.y : (c == 2) ? u.z : u.w;
            if (raw <= HTHR) {
                int pos = atomicAdd(&sW, 1);
                if (pos < CAP)
                    cc[pos] = ((uint64_t)fkey(raw) << 16) | (uint32_t)(8191 - (v * 4 + c));
            }
        }
    }
    __syncthreads();

    int W = sW;
    int ktrain = 0;
    bool done = false;

    if (W <= CAP) {
        // count(logit >= 0) from candidates: every such element passed the prefilter
        int cnt = 0;
        for (int i = tid; i < W; i += NT) cnt += (int)((cc[i] >> 47) & 1ull);
        cnt = __reduce_add_sync(0xFFFFFFFFu, cnt);
        if ((tid & 31) == 0) atomicAdd(&s_above, cnt);
        __syncthreads();
        ktrain = min(max(s_above, MINC), MAXC);

        if (W >= ktrain) {
            // ======== FAST PATH: exact top-k by pairwise rank (no barriers) =====
            for (int i = tid; i < W; i += NT) {
                uint64_t ci = cc[i];
                int rank = 0;
                #pragma unroll 4
                for (int j = 0; j < W; j++) rank += (cc[j] > ci);   // broadcast LDS.64
                if (rank < ktrain) {
                    int di = 8191 - (int)(ci & 0xFFFFu);
                    atomicOr(&bitmap[di >> 5], 1u << (di & 31));
                }
            }
            __syncthreads();
            done = true;
        }
    }

    if (!done) {
        // ======== SLOW PATH (prefilter miss — ~never): exact from global ========
        const float* in1 = (const float*)in4;
        const int4 z4 = make_int4(0, 0, 0, 0);
        ((int4*)hist)[2 * tid] = z4; ((int4*)hist)[2 * tid + 1] = z4;
        if (tid == 0) s_above = 0;
        __syncthreads();
        for (int i = tid; i < KC; i += NT)
            atomicAdd(&hist[fkey(__float_as_uint(in1[i])) >> 21], 1);
        __syncthreads();
        int h[8];
        {
            int4 a = ((int4*)hist)[2 * tid];
            int4 bb = ((int4*)hist)[2 * tid + 1];
            h[0]=a.x;h[1]=a.y;h[2]=a.z;h[3]=a.w;h[4]=bb.x;h[5]=bb.y;h[6]=bb.z;h[7]=bb.w;
            ((int4*)hist)[2 * tid] = z4; ((int4*)hist)[2 * tid + 1] = z4;
        }
        int local = h[0]+h[1]+h[2]+h[3]+h[4]+h[5]+h[6]+h[7];
        int above = block_suffix_excl(local, tid, wtmp);
        if (tid == 128) s_above = above + local;     // bins >= 1024 <=> logit >= 0
        __syncthreads();
        ktrain = min(max(s_above, MINC), MAXC);
        if (above < ktrain && above + local >= ktrain) {
            int run = above;
            for (int j = 7; j >= 0; j--) {
                int c = h[j];
                if (run < ktrain && run + c >= ktrain) { sctl[0] = tid * 8 + j; sctl[1] = ktrain - run; }
                run += c;
            }
        }
        __syncthreads();
        const uint32_t b = (uint32_t)sctl[0];

        if (tid == 0) sW = 0;
        __syncthreads();
        for (int i = tid; i < KC; i += NT) {
            uint32_t k2 = fkey(__float_as_uint(in1[i]));
            if ((k2 >> 21) >= b) {
                int pos = atomicAdd(&sW, 1);
                if (pos < CAP) cc[pos] = ((uint64_t)k2 << 16) | (uint32_t)(8191 - i);
            }
        }
        __syncthreads();
        W = sW;

        if (W <= CAP) {
            for (int i = tid; i < W; i += NT) {
                uint64_t ci = cc[i];
                int rank = 0;
                for (int j = 0; j < W; j++) rank += (cc[j] > ci);
                if (rank < ktrain) {
                    int di = 8191 - (int)(ci & 0xFFFFu);
                    atomicOr(&bitmap[di >> 5], 1u << (di & 31));
                }
            }
            __syncthreads();
        } else {
            // ---- ULTRA fallback: histogram refine to exact threshold ----
            const int need = sctl[1];
            for (int i = tid; i < KC; i += NT) {
                uint32_t k2 = fkey(__float_as_uint(in1[i]));
                if ((k2 >> 21) == b) atomicAdd(&hist[(k2 >> 10) & 0x7FF], 1);
            }
            __syncthreads();
            {
                int4 a = ((int4*)hist)[2 * tid];
                int4 bb = ((int4*)hist)[2 * tid + 1];
                h[0]=a.x;h[1]=a.y;h[2]=a.z;h[3]=a.w;h[4]=bb.x;h[5]=bb.y;h[6]=bb.z;h[7]=bb.w;
                ((int4*)hist)[2 * tid] = z4; ((int4*)hist)[2 * tid + 1] = z4;
            }
            local = h[0]+h[1]+h[2]+h[3]+h[4]+h[5]+h[6]+h[7];
            above = block_suffix_excl(local, tid, wtmp);
            if (above < need && above + local >= need) {
                int run = above;
                for (int j = 7; j >= 0; j--) {
                    int c = h[j];
                    if (run < need && run + c >= need) { sctl[2] = tid * 8 + j; sctl[3] = need - run; }
                    run += c;
                }
            }
            __syncthreads();
            const int need2 = sctl[3];
            const uint32_t pref22 = (b << 11) | (uint32_t)sctl[2];

            for (int i = tid; i < KC; i += NT) {
                uint32_t k2 = fkey(__float_as_uint(in1[i]));
                if ((k2 >> 10) == pref22) atomicAdd(&hist[k2 & 0x3FF], 1);
            }
            __syncthreads();
            {
                int4 a = ((int4*)hist)[tid];
                int h4[4] = {a.x, a.y, a.z, a.w};
                ((int4*)hist)[tid] = z4;
                int l3 = h4[0]+h4[1]+h4[2]+h4[3];
                int ab3 = block_suffix_excl(l3, tid, wtmp);
                if (ab3 < need2 && ab3 + l3 >= need2) {
                    int run = ab3;
                    for (int j = 3; j >= 0; j--) {
                        int c = h4[j];
                        if (run < need2 && run + c >= need2) { sctl[0] = tid * 4 + j; sctl[1] = need2 - run; }
                        run += c;
                    }
                }
            }
            __syncthreads();
            const uint32_t T = (pref22 << 10) | (uint32_t)sctl[0];
            const int need_eq = sctl[1];

            uint16_t* cidx = (uint16_t*)cc;     // scratch reuse
            if (tid == 0) sW = 0;
            __syncthreads();
            for (int i = tid; i < KC; i += NT) {
                uint32_t k2 = fkey(__float_as_uint(in1[i]));
                if (k2 > T) atomicOr(&bitmap[i >> 5], 1u << (i & 31));
                else if (k2 == T) {
                    int pos = atomicAdd(&sW, 1);
                    if (pos < CAP) cidx[pos] = (uint16_t)i;
                }
            }
            __syncthreads();
            int We = min(sW, CAP);
            for (int i = tid; i < We; i += NT) {
                int di = cidx[i];
                int rank = 0;
                for (int j = 0; j < We; j++) rank += ((int)cidx[j] < di);
                if (rank < need_eq) atomicOr(&bitmap[di >> 5], 1u << (di & 31));
            }
            __syncthreads();
        }
    }

    // ---- Emission: bitmap popcount + block prefix scan + bit walk ----
    uint32_t wbits = bitmap[tid];
    int cnt = __popc(wbits);
    int pos = block_prefix_excl(cnt, tid, wtmp);

    float* __restrict__ bs_out  = out;
    float* __restrict__ cls_out = out + (size_t)BSZ * MAXC;
    float* __restrict__ msk_out = out + (size_t)2 * BSZ * MAXC;
    const size_t rbase = (size_t)row * MAXC;

    while (wbits) {
        int bit = __ffs(wbits) - 1;
        wbits &= wbits - 1;
        cls_out[rbase + pos] = (float)(tid * 32 + bit);
        pos++;
    }

    // ---- Padding / bs_idx / mask ----
    if (tid < MAXC) {
        bs_out[rbase + tid] = (tid < ktrain) ? (float)row : -1.0f;
        if (tid >= ktrain) cls_out[rbase + tid] = -1.0f;
        msk_out[rbase + tid] = (tid < ktrain) ? 1.0f : 0.0f;
    }
}

extern "C" void kernel_launch(void* const* d_in, const int* in_sizes, int n_in,
                              void* d_out, int out_size)
{
    const float* logits = (const float*)d_in[0];
    float* out = (float*)d_out;
    retention_kernel<<<BSZ, NT>>>(logits, out);
}